// round 6
// baseline (speedup 1.0000x reference)
#include <cuda_runtime.h>
#include <cuda_fp16.h>

#define MAXN 100000

// ---- scratch (device globals; no runtime allocation allowed) ----
// g_svh: per node 128 halves = [a_src(64) | v(64)] -> 256B src-gather region
__device__ __align__(16) __half g_svh [MAXN * 128];
__device__ __align__(16) float  g_denom[MAXN * 64];
__device__ __align__(16) float  g_outh [MAXN * 64];

// vector reduction (no return) into global memory
__device__ __forceinline__ void red_add_f4(float* addr, float4 v) {
    asm volatile("red.global.add.v4.f32 [%0], {%1,%2,%3,%4};"
                 :: "l"(addr), "f"(v.x), "f"(v.y), "f"(v.z), "f"(v.w)
                 : "memory");
}

__device__ __forceinline__ uint4 pack8h(float4 a, float4 b) {
    uint4 r;
    *(__half2*)&r.x = __float22half2_rn(make_float2(a.x, a.y));
    *(__half2*)&r.y = __float22half2_rn(make_float2(a.z, a.w));
    *(__half2*)&r.z = __float22half2_rn(make_float2(b.x, b.y));
    *(__half2*)&r.w = __float22half2_rn(make_float2(b.z, b.w));
    return r;
}

// ---------------- node projections: a_src & v in one pass (+ zero denom/outh)
// grid: ceil(N/128), block 256; thread = (cg 0..15, ng 0..15) -> 8 nodes x 8 outs
__global__ void __launch_bounds__(256, 2) proj_kernel(
        const float* __restrict__ x,
        const float* __restrict__ Wl,
        const float* __restrict__ Wsrc,
        int N) {
    __shared__ float sW[64 * 128];      // [k][o]: o 0-63 a_src, 64-127 v
    __shared__ float sx[64 * 136];      // transposed x: [k][node 0..127]

    int tid  = threadIdx.x;
    int base = blockIdx.x * 128;

    float4 z = make_float4(0.f, 0.f, 0.f, 0.f);
    // zero denom/outh for this node range
    for (int i = tid; i < 2048; i += 256) {
        int n = i >> 4, c4 = i & 15;
        int node = base + n;
        if (node < N) {
            ((float4*)g_denom)[(size_t)node * 16 + c4] = z;
            ((float4*)g_outh) [(size_t)node * 16 + c4] = z;
        }
    }
    // W is [H=4][K=64][HD=16]; want sW[k*128 + (h*16+hd)] (+64 for Wl)
    for (int g = tid; g < 4096; g += 256) {
        int h = g >> 10, k = (g >> 4) & 63, hd = g & 15;
        int o = h * 16 + hd;
        sW[k * 128 + o]      = Wsrc[g];
        sW[k * 128 + 64 + o] = Wl[g];
    }
    // x tile [128 nodes][64 ch] -> transposed shared
    for (int i = tid; i < 2048; i += 256) {
        int n = i >> 4, c4 = i & 15;
        int node = base + n;
        float4 xv = (node < N) ? *(const float4*)(x + (size_t)node * 64 + c4 * 4) : z;
        int c = c4 * 4;
        sx[(c + 0) * 136 + n] = xv.x;
        sx[(c + 1) * 136 + n] = xv.y;
        sx[(c + 2) * 136 + n] = xv.z;
        sx[(c + 3) * 136 + n] = xv.w;
    }
    __syncthreads();

    int cg = tid & 15, ng = tid >> 4;
    float4 accA[8], accB[8];
#pragma unroll
    for (int i = 0; i < 8; i++) { accA[i] = z; accB[i] = z; }

#pragma unroll 4
    for (int k = 0; k < 64; k++) {
        float4 w0 = *(float4*)(sW + k * 128 + cg * 8);
        float4 w1 = *(float4*)(sW + k * 128 + cg * 8 + 4);
        float4 x0 = *(float4*)(sx + k * 136 + ng * 8);
        float4 x1 = *(float4*)(sx + k * 136 + ng * 8 + 4);
        float xs[8] = {x0.x, x0.y, x0.z, x0.w, x1.x, x1.y, x1.z, x1.w};
#pragma unroll
        for (int i = 0; i < 8; i++) {
            accA[i].x += xs[i] * w0.x;
            accA[i].y += xs[i] * w0.y;
            accA[i].z += xs[i] * w0.z;
            accA[i].w += xs[i] * w0.w;
            accB[i].x += xs[i] * w1.x;
            accB[i].y += xs[i] * w1.y;
            accB[i].z += xs[i] * w1.z;
            accB[i].w += xs[i] * w1.w;
        }
    }
#pragma unroll
    for (int i = 0; i < 8; i++) {
        int node = base + ng * 8 + i;
        if (node < N)
            *(uint4*)(g_svh + (size_t)node * 128 + cg * 8) = pack8h(accA[i], accB[i]);
    }
}

// ---------------- fused edge pass: denom += ex; outh += ex*(v+delta) --------
// a_dst cancels in the segment softmax (shift invariance) -> omitted.
// 8 lanes per edge, 8 channels (fp16-compressed gather) per lane.
__global__ void edge_fused_kernel(const int* __restrict__ ei,
                                  const float* __restrict__ pos,
                                  const float* __restrict__ Wpos,
                                  const float* __restrict__ bpos,
                                  int E, int Et) {
    int gid = blockIdx.x * 256 + threadIdx.x;
    int e = gid >> 3;
    if (e >= Et) return;
    int l = gid & 7;
    int s, d;
    if (e < E) { s = ei[e]; d = ei[E + e]; }
    else       { s = d = e - E; }

    // delta for channels c0 = l*8 .. l*8+7 (head h = l>>1, hd offset (l&1)*8)
    float rx = 0.f, ry = 0.f, rz = 0.f;
    if (s != d) {
        rx = pos[d * 3 + 0] - pos[s * 3 + 0];
        ry = pos[d * 3 + 1] - pos[s * 3 + 1];
        rz = pos[d * 3 + 2] - pos[s * 3 + 2];
    }
    int h = l >> 1, hd0 = (l & 1) * 8;
    const float* wp = Wpos + h * 48 + hd0;
    float4 wx0 = *(const float4*)(wp);
    float4 wx1 = *(const float4*)(wp + 4);
    float4 wy0 = *(const float4*)(wp + 16);
    float4 wy1 = *(const float4*)(wp + 20);
    float4 wz0 = *(const float4*)(wp + 32);
    float4 wz1 = *(const float4*)(wp + 36);
    const float* bp = bpos + h * 16 + hd0;
    float4 b0 = *(const float4*)(bp);
    float4 b1 = *(const float4*)(bp + 4);

    float4 dl0, dl1;
    dl0.x = b0.x + rx * wx0.x + ry * wy0.x + rz * wz0.x;
    dl0.y = b0.y + rx * wx0.y + ry * wy0.y + rz * wz0.y;
    dl0.z = b0.z + rx * wx0.z + ry * wy0.z + rz * wz0.z;
    dl0.w = b0.w + rx * wx0.w + ry * wy0.w + rz * wz0.w;
    dl1.x = b1.x + rx * wx1.x + ry * wy1.x + rz * wz1.x;
    dl1.y = b1.y + rx * wx1.y + ry * wy1.y + rz * wz1.y;
    dl1.z = b1.z + rx * wx1.z + ry * wy1.z + rz * wz1.z;
    dl1.w = b1.w + rx * wx1.w + ry * wy1.w + rz * wz1.w;

    // fp16 gathers: a_src and v, 8 channels each
    const __half* svp = g_svh + (size_t)s * 128 + l * 8;
    uint4 au = *(const uint4*)(svp);
    uint4 vu = *(const uint4*)(svp + 64);
    float2 a01 = __half22float2(*(__half2*)&au.x);
    float2 a23 = __half22float2(*(__half2*)&au.y);
    float2 a45 = __half22float2(*(__half2*)&au.z);
    float2 a67 = __half22float2(*(__half2*)&au.w);
    float2 v01 = __half22float2(*(__half2*)&vu.x);
    float2 v23 = __half22float2(*(__half2*)&vu.y);
    float2 v45 = __half22float2(*(__half2*)&vu.z);
    float2 v67 = __half22float2(*(__half2*)&vu.w);

    float4 ex0, ex1, m0, m1;
    ex0.x = __expf(dl0.x - a01.x);
    ex0.y = __expf(dl0.y - a01.y);
    ex0.z = __expf(dl0.z - a23.x);
    ex0.w = __expf(dl0.w - a23.y);
    ex1.x = __expf(dl1.x - a45.x);
    ex1.y = __expf(dl1.y - a45.y);
    ex1.z = __expf(dl1.z - a67.x);
    ex1.w = __expf(dl1.w - a67.y);
    m0.x = ex0.x * (v01.x + dl0.x);
    m0.y = ex0.y * (v01.y + dl0.y);
    m0.z = ex0.z * (v23.x + dl0.z);
    m0.w = ex0.w * (v23.y + dl0.w);
    m1.x = ex1.x * (v45.x + dl1.x);
    m1.y = ex1.y * (v45.y + dl1.y);
    m1.z = ex1.z * (v67.x + dl1.z);
    m1.w = ex1.w * (v67.y + dl1.w);

    float* dbase = g_denom + (size_t)d * 64 + l * 8;
    red_add_f4(dbase,     ex0);
    red_add_f4(dbase + 4, ex1);
    float* obase = g_outh + (size_t)d * 64 + l * 8;
    red_add_f4(obase,     m0);
    red_add_f4(obase + 4, m1);
}

// ---------------- MLP: t = outh/denom; y = relu(t@W1+b1)@W2+b2 ----------------
// grid: ceil(N/64), block 256; thread = (cg, ng) -> 4 nodes x 4 channels
__global__ void __launch_bounds__(256) mlp_kernel(
        const float* __restrict__ W1,
        const float* __restrict__ b1,
        const float* __restrict__ W2,
        const float* __restrict__ b2,
        float* __restrict__ out, int N) {
    __shared__ float sW1[64 * 64];
    __shared__ float sW2[64 * 64];
    __shared__ float sx [64 * 68];
    int tid  = threadIdx.x;
    int base = blockIdx.x * 64;

    for (int g = tid; g < 4096; g += 256) { sW1[g] = W1[g]; sW2[g] = W2[g]; }

    // stage t = outh/denom, transposed
    for (int i = tid; i < 1024; i += 256) {
        int n = i >> 4, c4 = i & 15;
        int node = base + n;
        float4 o4 = make_float4(0.f, 0.f, 0.f, 0.f);
        float4 d4 = make_float4(1.f, 1.f, 1.f, 1.f);
        if (node < N) {
            o4 = ((const float4*)g_outh)[(size_t)node * 16 + c4];
            d4 = ((const float4*)g_denom)[(size_t)node * 16 + c4];
        }
        int c = c4 * 4;
        sx[(c + 0) * 68 + n] = o4.x / d4.x;
        sx[(c + 1) * 68 + n] = o4.y / d4.y;
        sx[(c + 2) * 68 + n] = o4.z / d4.z;
        sx[(c + 3) * 68 + n] = o4.w / d4.w;
    }
    __syncthreads();

    int cg = tid & 15, ng = tid >> 4;
    float4 bias = *(const float4*)(b1 + cg * 4);
    float4 acc[4];
#pragma unroll
    for (int i = 0; i < 4; i++) acc[i] = bias;

#pragma unroll 8
    for (int k = 0; k < 64; k++) {
        float4 w  = *(float4*)(sW1 + k * 64 + cg * 4);
        float4 xa = *(float4*)(sx + k * 68 + ng * 4);
        float xv[4] = {xa.x, xa.y, xa.z, xa.w};
#pragma unroll
        for (int i = 0; i < 4; i++) {
            acc[i].x += xv[i] * w.x;
            acc[i].y += xv[i] * w.y;
            acc[i].z += xv[i] * w.z;
            acc[i].w += xv[i] * w.w;
        }
    }
    __syncthreads();

    // write h = relu(acc) transposed back into sx
#pragma unroll
    for (int i = 0; i < 4; i++) {
        int n = ng * 4 + i;
        sx[(cg * 4 + 0) * 68 + n] = fmaxf(acc[i].x, 0.f);
        sx[(cg * 4 + 1) * 68 + n] = fmaxf(acc[i].y, 0.f);
        sx[(cg * 4 + 2) * 68 + n] = fmaxf(acc[i].z, 0.f);
        sx[(cg * 4 + 3) * 68 + n] = fmaxf(acc[i].w, 0.f);
    }
    __syncthreads();

    float4 bias2 = *(const float4*)(b2 + cg * 4);
#pragma unroll
    for (int i = 0; i < 4; i++) acc[i] = bias2;

#pragma unroll 8
    for (int k = 0; k < 64; k++) {
        float4 w  = *(float4*)(sW2 + k * 64 + cg * 4);
        float4 xa = *(float4*)(sx + k * 68 + ng * 4);
        float xv[4] = {xa.x, xa.y, xa.z, xa.w};
#pragma unroll
        for (int i = 0; i < 4; i++) {
            acc[i].x += xv[i] * w.x;
            acc[i].y += xv[i] * w.y;
            acc[i].z += xv[i] * w.z;
            acc[i].w += xv[i] * w.w;
        }
    }
#pragma unroll
    for (int i = 0; i < 4; i++) {
        int node = base + ng * 4 + i;
        if (node < N)
            *(float4*)(out + (size_t)node * 64 + cg * 4) = acc[i];
    }
}

extern "C" void kernel_launch(void* const* d_in, const int* in_sizes, int n_in,
                              void* d_out, int out_size) {
    const float* x    = (const float*)d_in[0];
    const float* pos  = (const float*)d_in[1];
    const int*   ei   = (const int*)d_in[2];
    const float* Wl   = (const float*)d_in[3];
    const float* Wsrc = (const float*)d_in[4];
    // d_in[5] = W_dst  (unused: cancels exactly in the segment softmax)
    const float* Wpos = (const float*)d_in[6];
    const float* bpos = (const float*)d_in[7];
    const float* W1   = (const float*)d_in[8];
    const float* b1   = (const float*)d_in[9];
    const float* W2   = (const float*)d_in[10];
    const float* b2   = (const float*)d_in[11];
    float* out = (float*)d_out;

    int N  = in_sizes[0] / 64;
    int E  = in_sizes[2] / 2;
    int Et = E + N;

    proj_kernel<<<(N + 127) / 128, 256>>>(x, Wl, Wsrc, N);

    int eg = (Et * 8 + 255) / 256;
    edge_fused_kernel<<<eg, 256>>>(ei, pos, Wpos, bpos, E, Et);

    mlp_kernel<<<(N + 63) / 64, 256>>>(W1, b1, W2, b2, out, N);
}

// round 7
// speedup vs baseline: 1.0043x; 1.0043x over previous
#include <cuda_runtime.h>
#include <cuda_fp16.h>

#define MAXN 100000

// ---- scratch (device globals; no runtime allocation allowed) ----
// g_svh: per node 128 halves = [a_src(64) | v(64)] -> 256B src-gather region
__device__ __align__(16) __half g_svh [MAXN * 128];
__device__ __align__(16) float  g_denom[MAXN * 64];
__device__ __align__(16) float  g_outh [MAXN * 64];

// vector reduction (no return) into global memory
__device__ __forceinline__ void red_add_f4(float* addr, float4 v) {
    asm volatile("red.global.add.v4.f32 [%0], {%1,%2,%3,%4};"
                 :: "l"(addr), "f"(v.x), "f"(v.y), "f"(v.z), "f"(v.w)
                 : "memory");
}

__device__ __forceinline__ uint4 pack8h(float4 a, float4 b) {
    uint4 r;
    *(__half2*)&r.x = __float22half2_rn(make_float2(a.x, a.y));
    *(__half2*)&r.y = __float22half2_rn(make_float2(a.z, a.w));
    *(__half2*)&r.z = __float22half2_rn(make_float2(b.x, b.y));
    *(__half2*)&r.w = __float22half2_rn(make_float2(b.z, b.w));
    return r;
}

// ---------------- node projections: a_src & v in one pass (+ zero denom/outh)
// grid: ceil(N/128), block 256; thread = (cg 0..15, ng 0..15) -> 8 nodes x 8 outs
__global__ void __launch_bounds__(256, 2) proj_kernel(
        const float* __restrict__ x,
        const float* __restrict__ Wl,
        const float* __restrict__ Wsrc,
        int N) {
    __shared__ float sW[64 * 128];      // [k][o]: o 0-63 a_src, 64-127 v
    __shared__ float sx[64 * 136];      // transposed x: [k][node 0..127]

    int tid  = threadIdx.x;
    int base = blockIdx.x * 128;

    float4 z = make_float4(0.f, 0.f, 0.f, 0.f);
    // zero denom/outh for this node range
    for (int i = tid; i < 2048; i += 256) {
        int n = i >> 4, c4 = i & 15;
        int node = base + n;
        if (node < N) {
            ((float4*)g_denom)[(size_t)node * 16 + c4] = z;
            ((float4*)g_outh) [(size_t)node * 16 + c4] = z;
        }
    }
    // W is [H=4][K=64][HD=16]; want sW[k*128 + (h*16+hd)] (+64 for Wl)
    for (int g = tid; g < 4096; g += 256) {
        int h = g >> 10, k = (g >> 4) & 63, hd = g & 15;
        int o = h * 16 + hd;
        sW[k * 128 + o]      = Wsrc[g];
        sW[k * 128 + 64 + o] = Wl[g];
    }
    // x tile [128 nodes][64 ch] -> transposed shared
    for (int i = tid; i < 2048; i += 256) {
        int n = i >> 4, c4 = i & 15;
        int node = base + n;
        float4 xv = (node < N) ? *(const float4*)(x + (size_t)node * 64 + c4 * 4) : z;
        int c = c4 * 4;
        sx[(c + 0) * 136 + n] = xv.x;
        sx[(c + 1) * 136 + n] = xv.y;
        sx[(c + 2) * 136 + n] = xv.z;
        sx[(c + 3) * 136 + n] = xv.w;
    }
    __syncthreads();

    int cg = tid & 15, ng = tid >> 4;
    float4 accA[8], accB[8];
#pragma unroll
    for (int i = 0; i < 8; i++) { accA[i] = z; accB[i] = z; }

#pragma unroll 4
    for (int k = 0; k < 64; k++) {
        float4 w0 = *(float4*)(sW + k * 128 + cg * 8);
        float4 w1 = *(float4*)(sW + k * 128 + cg * 8 + 4);
        float4 x0 = *(float4*)(sx + k * 136 + ng * 8);
        float4 x1 = *(float4*)(sx + k * 136 + ng * 8 + 4);
        float xs[8] = {x0.x, x0.y, x0.z, x0.w, x1.x, x1.y, x1.z, x1.w};
#pragma unroll
        for (int i = 0; i < 8; i++) {
            accA[i].x += xs[i] * w0.x;
            accA[i].y += xs[i] * w0.y;
            accA[i].z += xs[i] * w0.z;
            accA[i].w += xs[i] * w0.w;
            accB[i].x += xs[i] * w1.x;
            accB[i].y += xs[i] * w1.y;
            accB[i].z += xs[i] * w1.z;
            accB[i].w += xs[i] * w1.w;
        }
    }
#pragma unroll
    for (int i = 0; i < 8; i++) {
        int node = base + ng * 8 + i;
        if (node < N)
            *(uint4*)(g_svh + (size_t)node * 128 + cg * 8) = pack8h(accA[i], accB[i]);
    }
}

// ---------------- fused edge pass: denom += ex; outh += ex*(v+delta) --------
// a_dst cancels in the segment softmax (shift invariance) -> omitted.
// 8 lanes per edge, 8 channels (fp16-compressed gather) per lane.
__global__ void edge_fused_kernel(const int* __restrict__ ei,
                                  const float* __restrict__ pos,
                                  const float* __restrict__ Wpos,
                                  const float* __restrict__ bpos,
                                  int E, int Et) {
    int gid = blockIdx.x * 256 + threadIdx.x;
    int e = gid >> 3;
    if (e >= Et) return;
    int l = gid & 7;
    int s, d;
    if (e < E) { s = ei[e]; d = ei[E + e]; }
    else       { s = d = e - E; }

    // delta for channels c0 = l*8 .. l*8+7 (head h = l>>1, hd offset (l&1)*8)
    float rx = 0.f, ry = 0.f, rz = 0.f;
    if (s != d) {
        rx = pos[d * 3 + 0] - pos[s * 3 + 0];
        ry = pos[d * 3 + 1] - pos[s * 3 + 1];
        rz = pos[d * 3 + 2] - pos[s * 3 + 2];
    }
    int h = l >> 1, hd0 = (l & 1) * 8;
    const float* wp = Wpos + h * 48 + hd0;
    float4 wx0 = *(const float4*)(wp);
    float4 wx1 = *(const float4*)(wp + 4);
    float4 wy0 = *(const float4*)(wp + 16);
    float4 wy1 = *(const float4*)(wp + 20);
    float4 wz0 = *(const float4*)(wp + 32);
    float4 wz1 = *(const float4*)(wp + 36);
    const float* bp = bpos + h * 16 + hd0;
    float4 b0 = *(const float4*)(bp);
    float4 b1 = *(const float4*)(bp + 4);

    float4 dl0, dl1;
    dl0.x = b0.x + rx * wx0.x + ry * wy0.x + rz * wz0.x;
    dl0.y = b0.y + rx * wx0.y + ry * wy0.y + rz * wz0.y;
    dl0.z = b0.z + rx * wx0.z + ry * wy0.z + rz * wz0.z;
    dl0.w = b0.w + rx * wx0.w + ry * wy0.w + rz * wz0.w;
    dl1.x = b1.x + rx * wx1.x + ry * wy1.x + rz * wz1.x;
    dl1.y = b1.y + rx * wx1.y + ry * wy1.y + rz * wz1.y;
    dl1.z = b1.z + rx * wx1.z + ry * wy1.z + rz * wz1.z;
    dl1.w = b1.w + rx * wx1.w + ry * wy1.w + rz * wz1.w;

    // fp16 gathers: a_src and v, 8 channels each
    const __half* svp = g_svh + (size_t)s * 128 + l * 8;
    uint4 au = *(const uint4*)(svp);
    uint4 vu = *(const uint4*)(svp + 64);
    float2 a01 = __half22float2(*(__half2*)&au.x);
    float2 a23 = __half22float2(*(__half2*)&au.y);
    float2 a45 = __half22float2(*(__half2*)&au.z);
    float2 a67 = __half22float2(*(__half2*)&au.w);
    float2 v01 = __half22float2(*(__half2*)&vu.x);
    float2 v23 = __half22float2(*(__half2*)&vu.y);
    float2 v45 = __half22float2(*(__half2*)&vu.z);
    float2 v67 = __half22float2(*(__half2*)&vu.w);

    float4 ex0, ex1, m0, m1;
    ex0.x = __expf(dl0.x - a01.x);
    ex0.y = __expf(dl0.y - a01.y);
    ex0.z = __expf(dl0.z - a23.x);
    ex0.w = __expf(dl0.w - a23.y);
    ex1.x = __expf(dl1.x - a45.x);
    ex1.y = __expf(dl1.y - a45.y);
    ex1.z = __expf(dl1.z - a67.x);
    ex1.w = __expf(dl1.w - a67.y);
    m0.x = ex0.x * (v01.x + dl0.x);
    m0.y = ex0.y * (v01.y + dl0.y);
    m0.z = ex0.z * (v23.x + dl0.z);
    m0.w = ex0.w * (v23.y + dl0.w);
    m1.x = ex1.x * (v45.x + dl1.x);
    m1.y = ex1.y * (v45.y + dl1.y);
    m1.z = ex1.z * (v67.x + dl1.z);
    m1.w = ex1.w * (v67.y + dl1.w);

    float* dbase = g_denom + (size_t)d * 64 + l * 8;
    red_add_f4(dbase,     ex0);
    red_add_f4(dbase + 4, ex1);
    float* obase = g_outh + (size_t)d * 64 + l * 8;
    red_add_f4(obase,     m0);
    red_add_f4(obase + 4, m1);
}

// ---------------- MLP: t = outh/denom; y = relu(t@W1+b1)@W2+b2 ----------------
// grid: ceil(N/64), block 256; thread = (cg, ng) -> 4 nodes x 4 channels
__global__ void __launch_bounds__(256) mlp_kernel(
        const float* __restrict__ W1,
        const float* __restrict__ b1,
        const float* __restrict__ W2,
        const float* __restrict__ b2,
        float* __restrict__ out, int N) {
    __shared__ float sW1[64 * 64];
    __shared__ float sW2[64 * 64];
    __shared__ float sx [64 * 68];
    int tid  = threadIdx.x;
    int base = blockIdx.x * 64;

    for (int g = tid; g < 4096; g += 256) { sW1[g] = W1[g]; sW2[g] = W2[g]; }

    // stage t = outh/denom, transposed
    for (int i = tid; i < 1024; i += 256) {
        int n = i >> 4, c4 = i & 15;
        int node = base + n;
        float4 o4 = make_float4(0.f, 0.f, 0.f, 0.f);
        float4 d4 = make_float4(1.f, 1.f, 1.f, 1.f);
        if (node < N) {
            o4 = ((const float4*)g_outh)[(size_t)node * 16 + c4];
            d4 = ((const float4*)g_denom)[(size_t)node * 16 + c4];
        }
        int c = c4 * 4;
        sx[(c + 0) * 68 + n] = o4.x / d4.x;
        sx[(c + 1) * 68 + n] = o4.y / d4.y;
        sx[(c + 2) * 68 + n] = o4.z / d4.z;
        sx[(c + 3) * 68 + n] = o4.w / d4.w;
    }
    __syncthreads();

    int cg = tid & 15, ng = tid >> 4;
    float4 bias = *(const float4*)(b1 + cg * 4);
    float4 acc[4];
#pragma unroll
    for (int i = 0; i < 4; i++) acc[i] = bias;

#pragma unroll 8
    for (int k = 0; k < 64; k++) {
        float4 w  = *(float4*)(sW1 + k * 64 + cg * 4);
        float4 xa = *(float4*)(sx + k * 68 + ng * 4);
        float xv[4] = {xa.x, xa.y, xa.z, xa.w};
#pragma unroll
        for (int i = 0; i < 4; i++) {
            acc[i].x += xv[i] * w.x;
            acc[i].y += xv[i] * w.y;
            acc[i].z += xv[i] * w.z;
            acc[i].w += xv[i] * w.w;
        }
    }
    __syncthreads();

    // write h = relu(acc) transposed back into sx
#pragma unroll
    for (int i = 0; i < 4; i++) {
        int n = ng * 4 + i;
        sx[(cg * 4 + 0) * 68 + n] = fmaxf(acc[i].x, 0.f);
        sx[(cg * 4 + 1) * 68 + n] = fmaxf(acc[i].y, 0.f);
        sx[(cg * 4 + 2) * 68 + n] = fmaxf(acc[i].z, 0.f);
        sx[(cg * 4 + 3) * 68 + n] = fmaxf(acc[i].w, 0.f);
    }
    __syncthreads();

    float4 bias2 = *(const float4*)(b2 + cg * 4);
#pragma unroll
    for (int i = 0; i < 4; i++) acc[i] = bias2;

#pragma unroll 8
    for (int k = 0; k < 64; k++) {
        float4 w  = *(float4*)(sW2 + k * 64 + cg * 4);
        float4 xa = *(float4*)(sx + k * 68 + ng * 4);
        float xv[4] = {xa.x, xa.y, xa.z, xa.w};
#pragma unroll
        for (int i = 0; i < 4; i++) {
            acc[i].x += xv[i] * w.x;
            acc[i].y += xv[i] * w.y;
            acc[i].z += xv[i] * w.z;
            acc[i].w += xv[i] * w.w;
        }
    }
#pragma unroll
    for (int i = 0; i < 4; i++) {
        int node = base + ng * 4 + i;
        if (node < N)
            *(float4*)(out + (size_t)node * 64 + cg * 4) = acc[i];
    }
}

extern "C" void kernel_launch(void* const* d_in, const int* in_sizes, int n_in,
                              void* d_out, int out_size) {
    const float* x    = (const float*)d_in[0];
    const float* pos  = (const float*)d_in[1];
    const int*   ei   = (const int*)d_in[2];
    const float* Wl   = (const float*)d_in[3];
    const float* Wsrc = (const float*)d_in[4];
    // d_in[5] = W_dst  (unused: cancels exactly in the segment softmax)
    const float* Wpos = (const float*)d_in[6];
    const float* bpos = (const float*)d_in[7];
    const float* W1   = (const float*)d_in[8];
    const float* b1   = (const float*)d_in[9];
    const float* W2   = (const float*)d_in[10];
    const float* b2   = (const float*)d_in[11];
    float* out = (float*)d_out;

    int N  = in_sizes[0] / 64;
    int E  = in_sizes[2] / 2;
    int Et = E + N;

    proj_kernel<<<(N + 127) / 128, 256>>>(x, Wl, Wsrc, N);

    int eg = (Et * 8 + 255) / 256;
    edge_fused_kernel<<<eg, 256>>>(ei, pos, Wpos, bpos, E, Et);

    mlp_kernel<<<(N + 63) / 64, 256>>>(W1, b1, W2, b2, out, N);
}

// round 8
// speedup vs baseline: 1.2696x; 1.2642x over previous
#include <cuda_runtime.h>
#include <cuda_fp16.h>

#define MAXN 100000

// ---- scratch (device globals; no runtime allocation allowed) ----
// g_svh: per node 128 halves = [a_src(64) | v(64)] -> 256B src-gather region
__device__ __align__(16) __half g_svh [MAXN * 128];
__device__ __align__(16) float  g_denom[MAXN * 64];
__device__ __align__(16) float  g_outh [MAXN * 64];

// vector reduction (no return) into global memory
__device__ __forceinline__ void red_add_f4(float* addr, float4 v) {
    asm volatile("red.global.add.v4.f32 [%0], {%1,%2,%3,%4};"
                 :: "l"(addr), "f"(v.x), "f"(v.y), "f"(v.z), "f"(v.w)
                 : "memory");
}

__device__ __forceinline__ uint2 pack4h(float4 a) {
    uint2 r;
    *(__half2*)&r.x = __float22half2_rn(make_float2(a.x, a.y));
    *(__half2*)&r.y = __float22half2_rn(make_float2(a.z, a.w));
    return r;
}

// ---------------- node projections: a_src & v in one pass ----------------
// Also initializes denom/outh with the SELF-LOOP contribution (rel=0 -> delta
// = b_pos, and a_src/v are in registers here), so the edge kernel handles
// only real edges.
// grid: ceil(N/64), block 256; thread = (cg 0..15, ng 0..15) -> 4 nodes x 4 ch
__global__ void __launch_bounds__(256) proj_kernel(
        const float* __restrict__ x,
        const float* __restrict__ Wl,
        const float* __restrict__ Wsrc,
        const float* __restrict__ bpos,
        int N) {
    __shared__ float sWs[64 * 64];      // a_src weights [k][o]
    __shared__ float sWl[64 * 64];      // v weights     [k][o]
    __shared__ float sx [64 * 68];      // transposed x: [k][node]

    int tid  = threadIdx.x;
    int base = blockIdx.x * 64;

    // W is [H=4][K=64][HD=16]; want sW[k*64 + (h*16+hd)]
    for (int g = tid; g < 4096; g += 256) {
        int h = g >> 10, k = (g >> 4) & 63, hd = g & 15;
        int o = h * 16 + hd;
        sWs[k * 64 + o] = Wsrc[g];
        sWl[k * 64 + o] = Wl[g];
    }
    // x tile [64 nodes][64 ch] -> transposed shared
    for (int i = tid; i < 1024; i += 256) {
        int n = i >> 4, c4 = i & 15;
        int node = base + n;
        float4 xv = (node < N) ? *(const float4*)(x + (size_t)node * 64 + c4 * 4)
                               : make_float4(0.f, 0.f, 0.f, 0.f);
        int c = c4 * 4;
        sx[(c + 0) * 68 + n] = xv.x;
        sx[(c + 1) * 68 + n] = xv.y;
        sx[(c + 2) * 68 + n] = xv.z;
        sx[(c + 3) * 68 + n] = xv.w;
    }
    __syncthreads();

    int cg = tid & 15, ng = tid >> 4;
    float4 accS[4], accV[4];
#pragma unroll
    for (int i = 0; i < 4; i++) {
        accS[i] = make_float4(0.f, 0.f, 0.f, 0.f);
        accV[i] = make_float4(0.f, 0.f, 0.f, 0.f);
    }

#pragma unroll 8
    for (int k = 0; k < 64; k++) {
        float4 ws = *(float4*)(sWs + k * 64 + cg * 4);
        float4 wl = *(float4*)(sWl + k * 64 + cg * 4);
        float4 xa = *(float4*)(sx + k * 68 + ng * 4);
        float xv[4] = {xa.x, xa.y, xa.z, xa.w};
#pragma unroll
        for (int i = 0; i < 4; i++) {
            accS[i].x += xv[i] * ws.x;
            accS[i].y += xv[i] * ws.y;
            accS[i].z += xv[i] * ws.z;
            accS[i].w += xv[i] * ws.w;
            accV[i].x += xv[i] * wl.x;
            accV[i].y += xv[i] * wl.y;
            accV[i].z += xv[i] * wl.z;
            accV[i].w += xv[i] * wl.w;
        }
    }

    // bpos flat is already channel-ordered [H*HD = 64]
    float4 b4 = *(const float4*)(bpos + cg * 4);

#pragma unroll
    for (int i = 0; i < 4; i++) {
        int node = base + ng * 4 + i;
        if (node < N) {
            // fp16-compressed gather arrays
            __half* p = g_svh + (size_t)node * 128;
            *(uint2*)(p + cg * 4)      = pack4h(accS[i]);   // a_src
            *(uint2*)(p + 64 + cg * 4) = pack4h(accV[i]);   // v

            // self-loop init: ex = exp(bpos - a_src); outh = ex*(v + bpos)
            float4 ex, m;
            ex.x = __expf(b4.x - accS[i].x);
            ex.y = __expf(b4.y - accS[i].y);
            ex.z = __expf(b4.z - accS[i].z);
            ex.w = __expf(b4.w - accS[i].w);
            m.x = ex.x * (accV[i].x + b4.x);
            m.y = ex.y * (accV[i].y + b4.y);
            m.z = ex.z * (accV[i].z + b4.z);
            m.w = ex.w * (accV[i].w + b4.w);
            *(float4*)(g_denom + (size_t)node * 64 + cg * 4) = ex;
            *(float4*)(g_outh  + (size_t)node * 64 + cg * 4) = m;
        }
    }
}

// ---------------- fused edge pass (real edges only) -------------------------
// a_dst cancels in the segment softmax (shift invariance) -> omitted.
// 16 lanes per edge, 4 channels per lane (fp16-compressed gathers).
__global__ void edge_fused_kernel(const int* __restrict__ ei,
                                  const float* __restrict__ pos,
                                  const float* __restrict__ Wpos,
                                  const float* __restrict__ bpos,
                                  int E) {
    int gid = blockIdx.x * 256 + threadIdx.x;
    int e = gid >> 4;
    if (e >= E) return;
    int l = gid & 15;
    int s = ei[e];
    int d = ei[E + e];

    // delta for channels c = l*4 .. l*4+3  (head h = l>>2, hd0 = (l&3)*4)
    float rx = pos[d * 3 + 0] - pos[s * 3 + 0];
    float ry = pos[d * 3 + 1] - pos[s * 3 + 1];
    float rz = pos[d * 3 + 2] - pos[s * 3 + 2];

    int h = l >> 2, hd0 = (l & 3) * 4;
    float4 wx = *(const float4*)(Wpos + h * 48 + hd0);
    float4 wy = *(const float4*)(Wpos + h * 48 + 16 + hd0);
    float4 wz = *(const float4*)(Wpos + h * 48 + 32 + hd0);
    float4 b  = *(const float4*)(bpos + h * 16 + hd0);
    float4 dl;
    dl.x = b.x + rx * wx.x + ry * wy.x + rz * wz.x;
    dl.y = b.y + rx * wx.y + ry * wy.y + rz * wz.y;
    dl.z = b.z + rx * wx.z + ry * wy.z + rz * wz.z;
    dl.w = b.w + rx * wx.w + ry * wy.w + rz * wz.w;

    // fp16 gathers: 4 channels of a_src and v (8B each)
    const __half* svp = g_svh + (size_t)s * 128 + l * 4;
    uint2 au = *(const uint2*)(svp);
    uint2 vu = *(const uint2*)(svp + 64);
    float2 a01 = __half22float2(*(__half2*)&au.x);
    float2 a23 = __half22float2(*(__half2*)&au.y);
    float2 v01 = __half22float2(*(__half2*)&vu.x);
    float2 v23 = __half22float2(*(__half2*)&vu.y);

    float4 ex, m;
    ex.x = __expf(dl.x - a01.x);
    ex.y = __expf(dl.y - a01.y);
    ex.z = __expf(dl.z - a23.x);
    ex.w = __expf(dl.w - a23.y);
    m.x = ex.x * (v01.x + dl.x);
    m.y = ex.y * (v01.y + dl.y);
    m.z = ex.z * (v23.x + dl.z);
    m.w = ex.w * (v23.y + dl.w);

    red_add_f4(g_denom + (size_t)d * 64 + l * 4, ex);
    red_add_f4(g_outh  + (size_t)d * 64 + l * 4, m);
}

// ---------------- MLP: t = outh/denom; y = relu(t@W1+b1)@W2+b2 ----------------
// grid: ceil(N/64), block 256; thread = (cg, ng) -> 4 nodes x 4 channels
__global__ void __launch_bounds__(256) mlp_kernel(
        const float* __restrict__ W1,
        const float* __restrict__ b1,
        const float* __restrict__ W2,
        const float* __restrict__ b2,
        float* __restrict__ out, int N) {
    __shared__ float sW1[64 * 64];
    __shared__ float sW2[64 * 64];
    __shared__ float sx [64 * 68];
    int tid  = threadIdx.x;
    int base = blockIdx.x * 64;

    for (int g = tid; g < 4096; g += 256) { sW1[g] = W1[g]; sW2[g] = W2[g]; }

    // stage t = outh/denom, transposed
    for (int i = tid; i < 1024; i += 256) {
        int n = i >> 4, c4 = i & 15;
        int node = base + n;
        float4 o4 = make_float4(0.f, 0.f, 0.f, 0.f);
        float4 d4 = make_float4(1.f, 1.f, 1.f, 1.f);
        if (node < N) {
            o4 = ((const float4*)g_outh)[(size_t)node * 16 + c4];
            d4 = ((const float4*)g_denom)[(size_t)node * 16 + c4];
        }
        int c = c4 * 4;
        sx[(c + 0) * 68 + n] = o4.x / d4.x;
        sx[(c + 1) * 68 + n] = o4.y / d4.y;
        sx[(c + 2) * 68 + n] = o4.z / d4.z;
        sx[(c + 3) * 68 + n] = o4.w / d4.w;
    }
    __syncthreads();

    int cg = tid & 15, ng = tid >> 4;
    float4 bias = *(const float4*)(b1 + cg * 4);
    float4 acc[4];
#pragma unroll
    for (int i = 0; i < 4; i++) acc[i] = bias;

#pragma unroll 8
    for (int k = 0; k < 64; k++) {
        float4 w  = *(float4*)(sW1 + k * 64 + cg * 4);
        float4 xa = *(float4*)(sx + k * 68 + ng * 4);
        float xv[4] = {xa.x, xa.y, xa.z, xa.w};
#pragma unroll
        for (int i = 0; i < 4; i++) {
            acc[i].x += xv[i] * w.x;
            acc[i].y += xv[i] * w.y;
            acc[i].z += xv[i] * w.z;
            acc[i].w += xv[i] * w.w;
        }
    }
    __syncthreads();

    // write h = relu(acc) transposed back into sx
#pragma unroll
    for (int i = 0; i < 4; i++) {
        int n = ng * 4 + i;
        sx[(cg * 4 + 0) * 68 + n] = fmaxf(acc[i].x, 0.f);
        sx[(cg * 4 + 1) * 68 + n] = fmaxf(acc[i].y, 0.f);
        sx[(cg * 4 + 2) * 68 + n] = fmaxf(acc[i].z, 0.f);
        sx[(cg * 4 + 3) * 68 + n] = fmaxf(acc[i].w, 0.f);
    }
    __syncthreads();

    float4 bias2 = *(const float4*)(b2 + cg * 4);
#pragma unroll
    for (int i = 0; i < 4; i++) acc[i] = bias2;

#pragma unroll 8
    for (int k = 0; k < 64; k++) {
        float4 w  = *(float4*)(sW2 + k * 64 + cg * 4);
        float4 xa = *(float4*)(sx + k * 68 + ng * 4);
        float xv[4] = {xa.x, xa.y, xa.z, xa.w};
#pragma unroll
        for (int i = 0; i < 4; i++) {
            acc[i].x += xv[i] * w.x;
            acc[i].y += xv[i] * w.y;
            acc[i].z += xv[i] * w.z;
            acc[i].w += xv[i] * w.w;
        }
    }
#pragma unroll
    for (int i = 0; i < 4; i++) {
        int node = base + ng * 4 + i;
        if (node < N)
            *(float4*)(out + (size_t)node * 64 + cg * 4) = acc[i];
    }
}

extern "C" void kernel_launch(void* const* d_in, const int* in_sizes, int n_in,
                              void* d_out, int out_size) {
    const float* x    = (const float*)d_in[0];
    const float* pos  = (const float*)d_in[1];
    const int*   ei   = (const int*)d_in[2];
    const float* Wl   = (const float*)d_in[3];
    const float* Wsrc = (const float*)d_in[4];
    // d_in[5] = W_dst  (unused: cancels exactly in the segment softmax)
    const float* Wpos = (const float*)d_in[6];
    const float* bpos = (const float*)d_in[7];
    const float* W1   = (const float*)d_in[8];
    const float* b1   = (const float*)d_in[9];
    const float* W2   = (const float*)d_in[10];
    const float* b2   = (const float*)d_in[11];
    float* out = (float*)d_out;

    int N  = in_sizes[0] / 64;
    int E  = in_sizes[2] / 2;

    proj_kernel<<<(N + 63) / 64, 256>>>(x, Wl, Wsrc, bpos, N);

    int eg = (E * 16 + 255) / 256;
    edge_fused_kernel<<<eg, 256>>>(ei, pos, Wpos, bpos, E);

    mlp_kernel<<<(N + 63) / 64, 256>>>(W1, b1, W2, b2, out, N);
}